// round 16
// baseline (speedup 1.0000x reference)
#include <cuda_runtime.h>
#include <math.h>
#include <stdint.h>

// ---------------------------------------------------------------------------
// Model_Recursive_LSTM_v2 — 3xBF16 GEMM (pre-packed hi/lo, cp.async pipeline)
// + fused LSTM epilogue + fused concat (dual-source A loader).
// B=256, L=64 (only 0..47 used), IN=1024, E=180.
// ---------------------------------------------------------------------------

#define E_DIM 180
#define G_DIM 720
#define M_CE  12288
#define S_CL  1536
#define S_MID 768
#define S_RT  256

// ---- scratch offsets (float words) ----
#define OFF_ASTP  0UL
#define OFF_E0P   12582912UL
#define OFF_E1P   20054016UL
#define OFF_E2P   24379392UL
#define OFF_EDP   26935296UL
#define OFF_XG    29294592UL
#define OFF_HAP   39247872UL
#define OFF_CA    39542784UL
#define OFF_T2P   40384512UL
#define OFF_LFP   40704000UL
#define OFF_XGM   40998912UL
#define OFF_HMP   42104832UL
#define OFF_CM    42252288UL
#define OFF_MDP   42390528UL
#define OFF_XGR   42537984UL
#define OFF_HRP   43090944UL
#define OFF_CR    43140096UL
#define OFF_PGP   43186176UL
#define OFF_R0P   43235328UL
#define OFF_R1    43288576UL
#define OFF_W0P   43334656UL
#define OFF_W1P   43949056UL
#define OFF_W2P   44161856UL
#define OFF_W3P   44232256UL
#define OFF_CW0P  44269696UL          // 200x384 packed
#define OFF_CW1P  44346496UL
#define OFF_RW0P  44386816UL
#define OFF_RW1P  44425216UL
#define OFF_CLIP  44465536UL
#define OFF_CLHP  44603776UL
#define OFF_NLIP  44742016UL
#define OFF_NLHP  44880256UL
#define OFF_NCP   45018496UL
#define OFF_NNP   45018688UL
#define OFF_HAP2  45018880UL          // 1536*192
#define OFF_HMP2  45313792UL          // 768*192
#define OFF_HRP2  45461248UL          // 256*192
#define SCRATCH_F 45510400UL

__device__ float4 g_scratch4[SCRATCH_F / 4];

__device__ __forceinline__ uint2 bfsplit2(float v0, float v1) {
    uint32_t hp;
    asm("cvt.rn.bf16x2.f32 %0, %1, %2;" : "=r"(hp) : "f"(v1), "f"(v0));
    float h0 = __uint_as_float(hp << 16);
    float h1 = __uint_as_float(hp & 0xffff0000u);
    uint32_t lp;
    asm("cvt.rn.bf16x2.f32 %0, %1, %2;" : "=r"(lp) : "f"(v1 - h1), "f"(v0 - h0));
    return make_uint2(hp, lp);
}

__device__ __forceinline__ long widx(long row, int k, int Kp) {
    int kp = k >> 1;
    int q = kp & 7;
    return row * Kp + (long)((kp >> 3) * 16 + (q & 3) * 4 + (q >> 2) * 2);
}

__device__ __forceinline__ void mma_bf16(float* d, const uint32_t* a, const uint32_t* b) {
    asm volatile(
        "mma.sync.aligned.m16n8k16.row.col.f32.bf16.bf16.f32 "
        "{%0,%1,%2,%3}, {%4,%5,%6,%7}, {%8,%9}, {%0,%1,%2,%3};"
        : "+f"(d[0]), "+f"(d[1]), "+f"(d[2]), "+f"(d[3])
        : "r"(a[0]), "r"(a[1]), "r"(a[2]), "r"(a[3]),
          "r"(b[0]), "r"(b[1]));
}

__device__ __forceinline__ uint32_t smem_u32(const void* p) {
    uint32_t a;
    asm("{ .reg .u64 t; cvta.to.shared.u64 t, %1; cvt.u32.u64 %0, t; }"
        : "=r"(a) : "l"(p));
    return a;
}

__device__ __forceinline__ void cpa16(uint32_t dst, const void* src, uint32_t bytes) {
    asm volatile("cp.async.cg.shared.global [%0], [%1], 16, %2;"
                 :: "r"(dst), "l"(src), "r"(bytes) : "memory");
}
#define CP_COMMIT() asm volatile("cp.async.commit_group;" ::: "memory")
#define CP_WAIT(n)  asm volatile("cp.async.wait_group %0;" :: "n"(n) : "memory")

__device__ __forceinline__ float sigf(float x) { return 1.f / (1.f + expf(-x)); }

extern __shared__ uint32_t dynsmem[];

// ---------------------------------------------------------------------------
// Packed 3xBF16 GEMM. NSTG=7: paired-slab loop; NSTG=4: per-slab loop.
// FUSE=1: LSTM pointwise epilogue. CATF=1: A = [src1(192) | src2(192)] virtual
// concat (slabs 0-11 from Ap, 12-23 from Ap2; fB/sB broadcast row 0).
// ---------------------------------------------------------------------------
template <int BMT, int WMT, int WNT, int MINB, int NSTG, int FUSE, int CATF>
__global__ __launch_bounds__(2 * BMT, MINB) void mma_gemm_pk(
    const uint4* __restrict__ Ap, const uint4* __restrict__ Wp,
    const float* __restrict__ bias, void* __restrict__ Cout,
    int M, int N, int Kp, int act, int Npck,
    const float* __restrict__ xg, const float* __restrict__ bih,
    const float* __restrict__ bhh, float* __restrict__ cst,
    uint32_t* __restrict__ hOut, int tstep, int divA, int mulA, int mulB,
    const uint4* __restrict__ Ap2, int fB, int sB)
{
    constexpr int MT = BMT / (WMT * 16);
    constexpr int NT = BMT / (WNT * 8);
    constexpr int RS = 4;
    constexpr int ARR_U4 = BMT * RS;
    constexpr int STAGE_U4 = 2 * ARR_U4;
    constexpr int STAGE_B = STAGE_U4 * 16;

    uint4* smem4 = reinterpret_cast<uint4*>(dynsmem);
    const uint32_t sbase = smem_u32(dynsmem);

    const int tid  = threadIdx.x;
    const int warp = tid >> 5;
    const int lane = tid & 31;
    const int wm = warp % WMT;
    const int wn = warp / WMT;
    const int bm = blockIdx.y * BMT;
    const int bn = blockIdx.x * BMT;
    const int grp = lane >> 2;
    const int tig = lane & 3;

    float acc[MT][NT][4];
#pragma unroll
    for (int i = 0; i < MT; i++)
#pragma unroll
        for (int j = 0; j < NT; j++)
#pragma unroll
            for (int r = 0; r < 4; r++) acc[i][j][r] = 0.f;

    const int arow = tid >> 1;
    const int half = tid & 1;
    const long rowU4 = (long)(Kp >> 2);
    const int brow = bn + arow;
    const bool bval = brow < N;
    const long bBase = (long)(bval ? brow : 0) * rowU4 + half * 2;
    const uint32_t bbytes = bval ? 16u : 0u;
    const uint32_t aDst0 = sbase + (uint32_t)(arow * RS + half * 2) * 16u;
    const uint32_t bDst0 = aDst0 + (uint32_t)ARR_U4 * 16u;

    const int nSlab = Kp >> 4;

    // A sources
    const uint4* aNxt;
    const uint4* a1 = nullptr;
    const uint4* a2 = nullptr;
    if constexpr (CATF == 1) {
        a1 = Ap  + (long)(fB ? 0 : (bm + arow)) * 48 + half * 2;   // width 192
        a2 = Ap2 + (long)(sB ? 0 : (bm + arow)) * 48 + half * 2;
        aNxt = nullptr;
    } else {
        aNxt = Ap + (long)(bm + arow) * rowU4 + half * 2;
    }
    const uint4* bNxt = Wp + bBase;
    int islab = 0;

    auto issueAt = [&](uint32_t so) {
        const uint4* as;
        if constexpr (CATF == 1) {
            as = (islab < 12) ? (a1 + islab * 4) : (a2 + (islab - 12) * 4);
        } else {
            as = aNxt;
            aNxt += 4;
        }
        cpa16(aDst0 + so,       as,     16u);
        cpa16(aDst0 + so + 16u, as + 1, 16u);
        cpa16(bDst0 + so,       bNxt,     bbytes);
        cpa16(bDst0 + so + 16u, bNxt + 1, bbytes);
        bNxt += 4;
        islab++;
    };

    uint32_t offA[MT][2], offB[NT];
#pragma unroll
    for (int mt = 0; mt < MT; mt++) {
        int mr = wm * MT * 16 + mt * 16 + grp;
        offA[mt][0] = (uint32_t)((mr * RS + tig) * 16);
        offA[mt][1] = (uint32_t)(((mr + 8) * RS + tig) * 16);
    }
#pragma unroll
    for (int nt = 0; nt < NT; nt++) {
        int nc = wn * NT * 8 + nt * 8 + grp;
        offB[nt] = (uint32_t)((ARR_U4 + nc * RS + tig) * 16);
    }
    const char* sbytes = (const char*)smem4;

    auto computeAt = [&](uint32_t so) {
        const char* sb = sbytes + so;
        uint32_t ah[MT][4], al[MT][4];
        uint32_t bh[NT][2], bl[NT][2];
#pragma unroll
        for (int mt = 0; mt < MT; mt++) {
            uint4 p0 = *(const uint4*)(sb + offA[mt][0]);
            uint4 p1 = *(const uint4*)(sb + offA[mt][1]);
            ah[mt][0] = p0.x; ah[mt][1] = p1.x; ah[mt][2] = p0.z; ah[mt][3] = p1.z;
            al[mt][0] = p0.y; al[mt][1] = p1.y; al[mt][2] = p0.w; al[mt][3] = p1.w;
        }
#pragma unroll
        for (int nt = 0; nt < NT; nt++) {
            uint4 q = *(const uint4*)(sb + offB[nt]);
            bh[nt][0] = q.x; bh[nt][1] = q.z;
            bl[nt][0] = q.y; bl[nt][1] = q.w;
        }
#pragma unroll
        for (int mt = 0; mt < MT; mt++)
#pragma unroll
            for (int nt = 0; nt < NT; nt++) {
                mma_bf16(acc[mt][nt], ah[mt], bl[nt]);
                mma_bf16(acc[mt][nt], al[mt], bh[nt]);
                mma_bf16(acc[mt][nt], ah[mt], bh[nt]);
            }
    };

    if constexpr (NSTG == 7) {
#pragma unroll
        for (int s = 0; s < 5; s++) {
            if (s < nSlab) issueAt((uint32_t)(s * STAGE_B));
            CP_COMMIT();
        }
        constexpr uint32_t WRAP = 7u * STAGE_B;
        uint32_t co = 0;
        uint32_t io = 5u * STAGE_B;
        int slab = 0;
        for (; slab + 1 < nSlab; slab += 2) {
            CP_WAIT(3);
            __syncthreads();
            if (slab + 5 < nSlab) issueAt(io);
            CP_COMMIT();
            io += STAGE_B; if (io >= WRAP) io -= WRAP;
            computeAt(co);
            co += STAGE_B; if (co >= WRAP) co -= WRAP;
            if (slab + 6 < nSlab) issueAt(io);
            CP_COMMIT();
            io += STAGE_B; if (io >= WRAP) io -= WRAP;
            computeAt(co);
            co += STAGE_B; if (co >= WRAP) co -= WRAP;
        }
        if (slab < nSlab) {
            CP_WAIT(0);
            __syncthreads();
            computeAt(co);
        }
    } else {
#pragma unroll
        for (int s = 0; s < 3; s++) {
            if (s < nSlab) issueAt((uint32_t)(s * STAGE_B));
            CP_COMMIT();
        }
        auto gstep = [&](int slabi, int stage) {
            CP_WAIT(2);
            __syncthreads();
            if (slabi + 3 < nSlab) issueAt((uint32_t)(((slabi + 3) & 3) * STAGE_B));
            CP_COMMIT();
            computeAt((uint32_t)(stage * STAGE_B));
        };
        int slab = 0;
        const int fullN = nSlab & ~3;
        for (; slab < fullN; slab += 4) {
            gstep(slab + 0, 0);
            gstep(slab + 1, 1);
            gstep(slab + 2, 2);
            gstep(slab + 3, 3);
        }
        for (; slab < nSlab; slab++) gstep(slab, slab & 3);
    }

    if constexpr (FUSE == 1) {
        // ---- fused LSTM epilogue (BMT==64, 128 threads) ----
        float* sg = (float*)dynsmem;       // [64][68]
        __syncthreads();
#pragma unroll
        for (int mt = 0; mt < MT; mt++) {
#pragma unroll
            for (int nt = 0; nt < NT; nt++) {
#pragma unroll
                for (int hh = 0; hh < 2; hh++) {
#pragma unroll
                    for (int q = 0; q < 2; q++) {
                        int rl = wm * MT * 16 + mt * 16 + grp + hh * 8;
                        int cl = wn * NT * 8 + nt * 8 + tig * 2 + q;
                        sg[rl * 68 + cl] = acc[mt][nt][hh * 2 + q];
                    }
                }
            }
        }
        __syncthreads();

        const int ebase0 = bn >> 2;
        for (int it = tid; it < 64 * 8; it += 128) {
            int ls = it >> 3, pe = it & 7;
            int s = bm + ls;
            int e0 = ebase0 + pe * 2;
            if (e0 >= 192) continue;
            uint2 p = make_uint2(0, 0);
            if (e0 < E_DIM) {
                int xrow = (s / divA) * mulA + (s % divA) * mulB + tstep;
                const float* xr = xg + (long)xrow * G_DIM;
                float hv[2];
#pragma unroll
                for (int l = 0; l < 2; l++) {
                    int e = e0 + l;
                    float g[4];
#pragma unroll
                    for (int gg = 0; gg < 4; gg++)
                        g[gg] = sg[ls * 68 + pe * 8 + l * 4 + gg]
                              + xr[4 * e + gg] + bih[gg * E_DIM + e] + bhh[gg * E_DIM + e];
                    float cp = cst[(long)s * E_DIM + e];
                    float cn = sigf(g[1]) * cp + sigf(g[0]) * tanhf(g[2]);
                    cst[(long)s * E_DIM + e] = cn;
                    hv[l] = sigf(g[3]) * tanhf(cn);
                }
                p = bfsplit2(hv[0], hv[1]);
            }
            *(uint2*)(hOut + widx((long)s, e0, 192)) = p;
        }
        return;
    }

    // ---- standard epilogue ----
    if (Npck > 0) {
        uint32_t* Cw = (uint32_t*)Cout;
#pragma unroll
        for (int mt = 0; mt < MT; mt++) {
            int r0 = bm + wm * MT * 16 + mt * 16 + grp;
#pragma unroll
            for (int nt = 0; nt < NT; nt++) {
                int cc = bn + wn * NT * 8 + nt * 8 + tig * 2;
                if (cc >= Npck) continue;
#pragma unroll
                for (int hh = 0; hh < 2; hh++) {
                    int rr = r0 + hh * 8;
                    float v0 = 0.f, v1 = 0.f;
                    if (cc < N) {
                        v0 = acc[mt][nt][hh * 2];
                        if (bias) v0 += bias[cc];
                        if (act) v0 = v0 > 0.f ? v0 : (expf(v0) - 1.f);
                    }
                    if (cc + 1 < N) {
                        v1 = acc[mt][nt][hh * 2 + 1];
                        if (bias) v1 += bias[cc + 1];
                        if (act) v1 = v1 > 0.f ? v1 : (expf(v1) - 1.f);
                    }
                    uint2 p = bfsplit2(v0, v1);
                    *(uint2*)(Cw + widx((long)rr, cc, Npck)) = p;
                }
            }
        }
    } else {
        float* Cf = (float*)Cout;
#pragma unroll
        for (int mt = 0; mt < MT; mt++) {
            int r0 = bm + wm * MT * 16 + mt * 16 + grp;
#pragma unroll
            for (int nt = 0; nt < NT; nt++) {
                int cc = bn + wn * NT * 8 + nt * 8 + tig * 2;
#pragma unroll
                for (int hh = 0; hh < 2; hh++) {
                    int rr = r0 + hh * 8;
#pragma unroll
                    for (int q = 0; q < 2; q++) {
                        int gn = cc + q;
                        if (gn >= N) continue;
                        float v = acc[mt][nt][hh * 2 + q];
                        if (bias) v += bias[gn];
                        if (act) v = v > 0.f ? v : (expf(v) - 1.f);
                        Cf[(long)rr * N + gn] = v;
                    }
                }
            }
        }
    }
}

#define SMEM_L (7 * 2 * 128 * 4 * 16)   // 114688
#define SMEM_S (4 * 2 * 64 * 4 * 16)    // 32768

// ---------------------------------------------------------------------------
// Pack kernels. mode 0: plain; 1: gate-interleave rows; 2: concat col remap
// (packed col j: j<180 -> j ; 192<=j<372 -> j-12 ; else zero).
// ---------------------------------------------------------------------------
#define NPACK 14
struct PackTable {
    const float* src[NPACK];
    float* dst[NPACK];
    int rows[NPACK];
    int K[NPACK];
    int Kp[NPACK];
    int mode[NPACK];
};

__global__ void pack_many_kernel(PackTable pt) {
    int which = blockIdx.y;
    int rows = pt.rows[which], K = pt.K[which], Kp = pt.Kp[which];
    int mode = pt.mode[which];
    int pairs = Kp >> 1;
    long n = (long)rows * pairs;
    long idx = (long)blockIdx.x * blockDim.x + threadIdx.x;
    if (idx >= n) return;
    int r = (int)(idx / pairs);
    int k = (int)(idx % pairs) * 2;
    int sr = (mode == 1) ? ((r & 3) * E_DIM + (r >> 2)) : r;
    const float* s = pt.src[which] + (long)sr * K;
    float v0, v1;
    if (mode == 2) {
        int k0 = (k < 180) ? k : ((k >= 192 && k < 372) ? k - 12 : -1);
        v0 = (k0 >= 0 && k0 < K) ? s[k0] : 0.f;
        v1 = (k0 >= 0 && k0 + 1 < K) ? s[k0 + 1] : 0.f;
    } else {
        v0 = (k < K) ? s[k] : 0.f;
        v1 = (k + 1 < K) ? s[k + 1] : 0.f;
    }
    uint2 p = bfsplit2(v0, v1);
    *(uint2*)((uint32_t*)pt.dst[which] + widx((long)r, k, Kp)) = p;
}

__global__ void pack_ast_kernel(const float* __restrict__ src, uint32_t* __restrict__ dst) {
    long idx = (long)blockIdx.x * blockDim.x + threadIdx.x;
    if (idx >= (long)M_CE * 512) return;
    int m = (int)(idx / 512);
    int k = (int)(idx % 512) * 2;
    long phys = (long)(m / 48) * 64 + (m % 48);
    const float* s = src + phys * 1024 + k;
    uint2 p = bfsplit2(s[0], s[1]);
    *(uint2*)(dst + widx((long)m, k, 1024)) = p;
}

// ---------------------------------------------------------------------------
// LSTM t=0 step (h0=c0=0); xg gate-interleaved (col = 4*e + gate).
// ---------------------------------------------------------------------------
__global__ void lstm_step0_kernel(
    const float* __restrict__ xg,
    const float* __restrict__ bih, const float* __restrict__ bhh,
    uint32_t* __restrict__ hP, float* __restrict__ c,
    int S, int divA, int mulA, int mulB)
{
    int idx = blockIdx.x * blockDim.x + threadIdx.x;
    if (idx >= S * 96) return;
    int s = idx / 96, pe = idx % 96;
    int e0 = pe * 2;
    uint2 p = make_uint2(0, 0);
    if (e0 < E_DIM) {
        int xrow = (s / divA) * mulA + (s % divA) * mulB;
        const float* xr = xg + (long)xrow * G_DIM;
        float hv[2];
#pragma unroll
        for (int l = 0; l < 2; l++) {
            int e = e0 + l;
            float g[4];
#pragma unroll
            for (int gg = 0; gg < 4; gg++)
                g[gg] = xr[4 * e + gg] + bih[gg * E_DIM + e] + bhh[gg * E_DIM + e];
            float cn = sigf(g[0]) * tanhf(g[2]);
            c[(long)s * E_DIM + e] = cn;
            hv[l] = sigf(g[3]) * tanhf(cn);
        }
        p = bfsplit2(hv[0], hv[1]);
    }
    *(uint2*)(hP + widx((long)s, e0, 192)) = p;
}

// ---------------------------------------------------------------------------
__global__ void pred_kernel(const float* __restrict__ x, const float* __restrict__ w,
                            const float* __restrict__ b, float* __restrict__ out, int rows)
{
    int gwarp = (blockIdx.x * blockDim.x + threadIdx.x) >> 5;
    int lane = threadIdx.x & 31;
    if (gwarp >= rows) return;
    float s = 0.f;
    for (int e = lane; e < E_DIM; e += 32) s += x[(long)gwarp * E_DIM + e] * w[e];
#pragma unroll
    for (int o = 16; o; o >>= 1) s += __shfl_down_sync(0xffffffffu, s, o);
    if (lane == 0) out[gwarp] = s + b[0];
}

// ---------------------------------------------------------------------------
// host side
// ---------------------------------------------------------------------------
static inline void gemm(const float* Ap, const float* Wp, const float* bias, void* C,
                        int M, int N, int Kp, int act, int Npck)
{
    int gL = ((N + 127) / 128) * (M / 128);
    if ((M % 128 == 0) && gL >= 96) {
        dim3 grid((N + 127) / 128, M / 128);
        mma_gemm_pk<128, 2, 4, 2, 7, 0, 0><<<grid, 256, SMEM_L>>>(
            (const uint4*)Ap, (const uint4*)Wp, bias, C, M, N, Kp, act, Npck,
            nullptr, nullptr, nullptr, nullptr, nullptr, 0, 1, 0, 0, nullptr, 0, 0);
    } else {
        dim3 grid((N + 63) / 64, M / 64);
        mma_gemm_pk<64, 2, 2, 4, 4, 0, 0><<<grid, 128, SMEM_S>>>(
            (const uint4*)Ap, (const uint4*)Wp, bias, C, M, N, Kp, act, Npck,
            nullptr, nullptr, nullptr, nullptr, nullptr, 0, 1, 0, 0, nullptr, 0, 0);
    }
}

// concat GEMM: A = [first(192) | second(192)] virtual, W packed Kp=384
static inline void gemm_cat(const float* first, int fB, const float* second, int sB,
                            const float* Wp, const float* bias, void* C,
                            int M, int N, int Npck)
{
    dim3 grid((N + 63) / 64, M / 64);
    mma_gemm_pk<64, 2, 2, 4, 4, 0, 1><<<grid, 128, SMEM_S>>>(
        (const uint4*)first, (const uint4*)Wp, bias, C, M, N, 384, 1, Npck,
        nullptr, nullptr, nullptr, nullptr, nullptr, 0, 1, 0, 0,
        (const uint4*)second, fB, sB);
}

// fused recurrent step: h_out = LSTM(xg[t], h_in @ Whh^T)
static inline void gemm_lstm(const float* hIn, const float* WhhP,
                             const float* xg, const float* bih, const float* bhh,
                             float* c, float* hOut, int S, int t,
                             int divA, int mulA, int mulB)
{
    dim3 grid((G_DIM + 63) / 64, S / 64);
    mma_gemm_pk<64, 2, 2, 4, 4, 1, 0><<<grid, 128, SMEM_S>>>(
        (const uint4*)hIn, (const uint4*)WhhP, nullptr, nullptr,
        S, G_DIM, 192, 0, 0,
        xg, bih, bhh, c, (uint32_t*)hOut, t, divA, mulA, mulB, nullptr, 0, 0);
}

extern "C" void kernel_launch(void* const* d_in, const int* in_sizes, int n_in,
                              void* d_out, int out_size)
{
    cudaFuncSetAttribute((const void*)mma_gemm_pk<128, 2, 4, 2, 7, 0, 0>,
                         cudaFuncAttributeMaxDynamicSharedMemorySize, SMEM_L);
    cudaFuncSetAttribute((const void*)mma_gemm_pk<64, 2, 2, 4, 4, 0, 0>,
                         cudaFuncAttributeMaxDynamicSharedMemorySize, SMEM_S);
    cudaFuncSetAttribute((const void*)mma_gemm_pk<64, 2, 2, 4, 4, 1, 0>,
                         cudaFuncAttributeMaxDynamicSharedMemorySize, SMEM_S);
    cudaFuncSetAttribute((const void*)mma_gemm_pk<64, 2, 2, 4, 4, 0, 1>,
                         cudaFuncAttributeMaxDynamicSharedMemorySize, SMEM_S);

    const float* ast    = (const float*)d_in[0];
    const float* ce_w0  = (const float*)d_in[1];  const float* ce_b0 = (const float*)d_in[2];
    const float* ce_w1  = (const float*)d_in[3];  const float* ce_b1 = (const float*)d_in[4];
    const float* ce_w2  = (const float*)d_in[5];  const float* ce_b2 = (const float*)d_in[6];
    const float* ce_w3  = (const float*)d_in[7];  const float* ce_b3 = (const float*)d_in[8];
    const float* cc_w0  = (const float*)d_in[9];  const float* cc_b0 = (const float*)d_in[10];
    const float* cc_w1  = (const float*)d_in[11]; const float* cc_b1 = (const float*)d_in[12];
    const float* rg_w0  = (const float*)d_in[13]; const float* rg_b0 = (const float*)d_in[14];
    const float* rg_w1  = (const float*)d_in[15]; const float* rg_b1 = (const float*)d_in[16];
    const float* pred_w = (const float*)d_in[17]; const float* pred_b = (const float*)d_in[18];
    const float* cl_Wih = (const float*)d_in[19]; const float* cl_Whh = (const float*)d_in[20];
    const float* cl_bih = (const float*)d_in[21]; const float* cl_bhh = (const float*)d_in[22];
    const float* nl_Wih = (const float*)d_in[23]; const float* nl_Whh = (const float*)d_in[24];
    const float* nl_bih = (const float*)d_in[25]; const float* nl_bhh = (const float*)d_in[26];
    const float* no_comps = (const float*)d_in[27];
    const float* no_nodes = (const float*)d_in[28];
    float* out = (float*)d_out;

    float* S0 = nullptr;
    cudaGetSymbolAddress((void**)&S0, g_scratch4);

    float* astP = S0 + OFF_ASTP;
    float* e0P = S0 + OFF_E0P;   float* e1P = S0 + OFF_E1P;
    float* e2P = S0 + OFF_E2P;   float* edP = S0 + OFF_EDP;
    float* xg  = S0 + OFF_XG;
    float* hA0 = S0 + OFF_HAP;   float* hA1 = S0 + OFF_HAP2;
    float* cA  = S0 + OFF_CA;
    float* t2P = S0 + OFF_T2P;   float* lfP = S0 + OFF_LFP;
    float* xgm = S0 + OFF_XGM;
    float* hM0 = S0 + OFF_HMP;   float* hM1 = S0 + OFF_HMP2;
    float* cM  = S0 + OFF_CM;
    float* mdP = S0 + OFF_MDP;   float* xgr = S0 + OFF_XGR;
    float* hR0 = S0 + OFF_HRP;   float* hR1 = S0 + OFF_HRP2;
    float* cR  = S0 + OFF_CR;
    float* pgP = S0 + OFF_PGP;   float* r0P = S0 + OFF_R0P;
    float* r1  = S0 + OFF_R1;
    float* w0P = S0 + OFF_W0P;   float* w1P = S0 + OFF_W1P;
    float* w2P = S0 + OFF_W2P;   float* w3P = S0 + OFF_W3P;
    float* cw0P = S0 + OFF_CW0P; float* cw1P = S0 + OFF_CW1P;
    float* rw0P = S0 + OFF_RW0P; float* rw1P = S0 + OFF_RW1P;
    float* clIP = S0 + OFF_CLIP; float* clHP = S0 + OFF_CLHP;
    float* nlIP = S0 + OFF_NLIP; float* nlHP = S0 + OFF_NLHP;
    float* ncP = S0 + OFF_NCP;   float* nnP = S0 + OFF_NNP;

    // ---- pack weights + constants ----
    PackTable pt;
    const float* srcs[NPACK] = { ce_w0, ce_w1, ce_w2, ce_w3, cc_w0, cc_w1, rg_w0, rg_w1,
                                 cl_Wih, cl_Whh, nl_Wih, nl_Whh, no_comps, no_nodes };
    float* dsts[NPACK] = { w0P, w1P, w2P, w3P, cw0P, cw1P, rw0P, rw1P,
                           clIP, clHP, nlIP, nlHP, ncP, nnP };
    int rws[NPACK] = { 600, 350, 200, 180, 200, 180, 200, 180, 720, 720, 720, 720, 1, 1 };
    int ks[NPACK]  = { 1024, 600, 350, 200, 360, 200, 180, 200, 180, 180, 180, 180, 180, 180 };
    int kps[NPACK] = { 1024, 608, 352, 208, 384, 208, 192, 208, 192, 192, 192, 192, 192, 192 };
    int mds[NPACK] = { 0, 0, 0, 0, 2, 0, 0, 0, 1, 1, 1, 1, 0, 0 };
    for (int i = 0; i < NPACK; i++) {
        pt.src[i] = srcs[i]; pt.dst[i] = dsts[i];
        pt.rows[i] = rws[i]; pt.K[i] = ks[i]; pt.Kp[i] = kps[i]; pt.mode[i] = mds[i];
    }
    {
        long maxn = 600L * 512;
        dim3 g((unsigned)((maxn + 255) / 256), NPACK);
        pack_many_kernel<<<g, 256>>>(pt);
    }
    pack_ast_kernel<<<(int)(((long)M_CE * 512 + 255) / 256), 256>>>(ast, (uint32_t*)astP);

    // ---- Phase A: comp-embedding MLP ----
    gemm(astP, w0P, ce_b0, e0P, M_CE, 600, 1024, 1, 608);
    gemm(e0P,  w1P, ce_b1, e1P, M_CE, 350, 608, 1, 352);
    gemm(e1P,  w2P, ce_b2, e2P, M_CE, 200, 352, 1, 208);
    gemm(e2P,  w3P, ce_b3, edP, M_CE, 180, 208, 1, 192);

    // ---- Phase B: cl LSTM (S=1536, T=8), fused steps ----
    gemm(edP, clIP, nullptr, xg, M_CE, G_DIM, 192, 0, 0);
    {
        int thr = S_CL * 96;
        lstm_step0_kernel<<<(thr + 255) / 256, 256>>>(xg, cl_bih, cl_bhh,
                                                      (uint32_t*)hA0, cA, S_CL, 6, 48, 8);
        float* cur = hA0; float* nxt = hA1;
        for (int t = 1; t < 8; t++) {
            gemm_lstm(cur, clHP, xg, cl_bih, cl_bhh, cA, nxt, S_CL, t, 6, 48, 8);
            float* tmp = cur; cur = nxt; nxt = tmp;
        }
        hA0 = cur;
    }

    // ---- Phase C: leaf concat block (concat fused into GEMM) ----
    gemm_cat(nnP, 1, hA0, 0, cw0P, cc_b0, t2P, S_CL, 200, 208);
    gemm(t2P, cw1P, cc_b1, lfP, S_CL, 180, 208, 1, 192);

    // ---- Phase D: mid nl LSTM (S=768, T=2), fused ----
    gemm(lfP, nlIP, nullptr, xgm, S_CL, G_DIM, 192, 0, 0);
    {
        int thr = S_MID * 96;
        lstm_step0_kernel<<<(thr + 255) / 256, 256>>>(xgm, nl_bih, nl_bhh,
                                                      (uint32_t*)hM0, cM, S_MID, 3, 6, 2);
        gemm_lstm(hM0, nlHP, xgm, nl_bih, nl_bhh, cM, hM1, S_MID, 1, 3, 6, 2);
    }

    // ---- Phase E: mid concat block ----
    gemm_cat(hM1, 0, ncP, 1, cw0P, cc_b0, t2P, S_MID, 200, 208);
    gemm(t2P, cw1P, cc_b1, mdP, S_MID, 180, 208, 1, 192);

    // ---- Phase F: root nl LSTM (S=256, T=3), fused ----
    gemm(mdP, nlIP, nullptr, xgr, S_MID, G_DIM, 192, 0, 0);
    {
        int thr = S_RT * 96;
        lstm_step0_kernel<<<(thr + 255) / 256, 256>>>(xgr, nl_bih, nl_bhh,
                                                      (uint32_t*)hR0, cR, S_RT, 1, 3, 0);
        gemm_lstm(hR0, nlHP, xgr, nl_bih, nl_bhh, cR, hR1, S_RT, 1, 1, 3, 0);
        gemm_lstm(hR1, nlHP, xgr, nl_bih, nl_bhh, cR, hR0, S_RT, 2, 1, 3, 0);
    }

    // ---- Phase G: root concat block ----
    gemm_cat(hR0, 0, ncP, 1, cw0P, cc_b0, t2P, S_RT, 200, 208);
    gemm(t2P, cw1P, cc_b1, pgP, S_RT, 180, 208, 1, 192);

    // ---- Phase H: regression head ----
    gemm(pgP, rw0P, rg_b0, r0P, S_RT, 200, 192, 1, 208);
    gemm(r0P, rw1P, rg_b1, r1, S_RT, 180, 208, 1, 0);
    pred_kernel<<<(S_RT * 32 + 255) / 256, 256>>>(r1, pred_w, pred_b, out, S_RT);
}

// round 17
// speedup vs baseline: 1.0539x; 1.0539x over previous
#include <cuda_runtime.h>
#include <math.h>
#include <stdint.h>

// ---------------------------------------------------------------------------
// Model_Recursive_LSTM_v2 — 3xBF16 GEMM (pre-packed hi/lo, 4-stage cp.async)
// + fused LSTM epilogue on recurrent GEMMs (gate-interleaved weights).
// B=256, L=64 (only 0..47 used), IN=1024, E=180.
//
// Packed layout (word = uint32): per row of padded width Kp (mult of 16),
// pair index kp=k/2, slab=kp>>3, q=kp&7:
//   word_off = slab*16 + (q&3)*4 + (q>>2)*2 ; word[off]=hi bf16x2, [off+1]=lo
// LSTM weights packed gate-interleaved: packed row n = src row (n&3)*180+(n>>2).
// ---------------------------------------------------------------------------

#define E_DIM 180
#define G_DIM 720
#define M_CE  12288
#define S_CL  1536
#define S_MID 768
#define S_RT  256

// ---- scratch offsets (float words) ----
#define OFF_ASTP  0UL
#define OFF_E0P   12582912UL
#define OFF_E1P   20054016UL
#define OFF_E2P   24379392UL
#define OFF_EDP   26935296UL
#define OFF_XG    29294592UL
#define OFF_HAP   39247872UL
#define OFF_CA    39542784UL
#define OFF_CATP  39819264UL
#define OFF_T2P   40384512UL
#define OFF_LFP   40704000UL
#define OFF_XGM   40998912UL
#define OFF_HMP   42104832UL
#define OFF_CM    42252288UL
#define OFF_MDP   42390528UL
#define OFF_XGR   42537984UL
#define OFF_HRP   43090944UL
#define OFF_CR    43140096UL
#define OFF_PGP   43186176UL
#define OFF_R0P   43235328UL
#define OFF_R1    43288576UL
#define OFF_W0P   43334656UL
#define OFF_W1P   43949056UL
#define OFF_W2P   44161856UL
#define OFF_W3P   44232256UL
#define OFF_CW0P  44269696UL
#define OFF_CW1P  44343296UL
#define OFF_RW0P  44380736UL
#define OFF_RW1P  44419136UL
#define OFF_CLIP  44456576UL
#define OFF_CLHP  44594816UL
#define OFF_NLIP  44733056UL
#define OFF_NLHP  44871296UL
#define OFF_NCP   45009536UL
#define OFF_NNP   45009728UL
#define OFF_HAP2  45009920UL            // 1536*192
#define OFF_HMP2  45304832UL            // 768*192
#define OFF_HRP2  45452288UL            // 256*192
#define SCRATCH_F 45501440UL

__device__ float4 g_scratch4[SCRATCH_F / 4];

__device__ __forceinline__ uint2 bfsplit2(float v0, float v1) {
    uint32_t hp;
    asm("cvt.rn.bf16x2.f32 %0, %1, %2;" : "=r"(hp) : "f"(v1), "f"(v0));
    float h0 = __uint_as_float(hp << 16);
    float h1 = __uint_as_float(hp & 0xffff0000u);
    uint32_t lp;
    asm("cvt.rn.bf16x2.f32 %0, %1, %2;" : "=r"(lp) : "f"(v1 - h1), "f"(v0 - h0));
    return make_uint2(hp, lp);
}

__device__ __forceinline__ long widx(long row, int k, int Kp) {
    int kp = k >> 1;
    int q = kp & 7;
    return row * Kp + (long)((kp >> 3) * 16 + (q & 3) * 4 + (q >> 2) * 2);
}

__device__ __forceinline__ void mma_bf16(float* d, const uint32_t* a, const uint32_t* b) {
    asm volatile(
        "mma.sync.aligned.m16n8k16.row.col.f32.bf16.bf16.f32 "
        "{%0,%1,%2,%3}, {%4,%5,%6,%7}, {%8,%9}, {%0,%1,%2,%3};"
        : "+f"(d[0]), "+f"(d[1]), "+f"(d[2]), "+f"(d[3])
        : "r"(a[0]), "r"(a[1]), "r"(a[2]), "r"(a[3]),
          "r"(b[0]), "r"(b[1]));
}

__device__ __forceinline__ uint32_t smem_u32(const void* p) {
    uint32_t a;
    asm("{ .reg .u64 t; cvta.to.shared.u64 t, %1; cvt.u32.u64 %0, t; }"
        : "=r"(a) : "l"(p));
    return a;
}

__device__ __forceinline__ void cpa16(uint32_t dst, const void* src, uint32_t bytes) {
    asm volatile("cp.async.cg.shared.global [%0], [%1], 16, %2;"
                 :: "r"(dst), "l"(src), "r"(bytes) : "memory");
}
#define CP_COMMIT() asm volatile("cp.async.commit_group;" ::: "memory")
#define CP_WAIT(n)  asm volatile("cp.async.wait_group %0;" :: "n"(n) : "memory")

__device__ __forceinline__ float sigf(float x) { return 1.f / (1.f + expf(-x)); }

extern __shared__ uint32_t dynsmem[];

// ---------------------------------------------------------------------------
// Packed 3xBF16 GEMM, 4-stage cp.async pipeline (R11 schedule).
// FUSE=1 (BMT=64): LSTM pointwise epilogue, h written packed (width 192).
// FUSE=0: Npck>0 packed-C epilogue; Npck==0 fp32-C epilogue.
// M multiple of BMT at every call site.
// ---------------------------------------------------------------------------
template <int BMT, int WMT, int WNT, int MINB, int FUSE>
__global__ __launch_bounds__(2 * BMT, MINB) void mma_gemm_pk(
    const uint4* __restrict__ Ap, const uint4* __restrict__ Wp,
    const float* __restrict__ bias, void* __restrict__ Cout,
    int M, int N, int Kp, int act, int Npck,
    const float* __restrict__ xg, const float* __restrict__ bih,
    const float* __restrict__ bhh, float* __restrict__ cst,
    uint32_t* __restrict__ hOut, int tstep, int divA, int mulA, int mulB)
{
    constexpr int MT = BMT / (WMT * 16);
    constexpr int NT = BMT / (WNT * 8);
    constexpr int RS = 4;                   // uint4 per row per slab
    constexpr int ARR_U4 = BMT * RS;
    constexpr int STAGE_U4 = 2 * ARR_U4;
    constexpr int STAGE_B = STAGE_U4 * 16;

    uint4* smem4 = reinterpret_cast<uint4*>(dynsmem);
    const uint32_t sbase = smem_u32(dynsmem);

    const int tid  = threadIdx.x;
    const int warp = tid >> 5;
    const int lane = tid & 31;
    const int wm = warp % WMT;
    const int wn = warp / WMT;
    const int bm = blockIdx.y * BMT;
    const int bn = blockIdx.x * BMT;
    const int grp = lane >> 2;
    const int tig = lane & 3;

    float acc[MT][NT][4];
#pragma unroll
    for (int i = 0; i < MT; i++)
#pragma unroll
        for (int j = 0; j < NT; j++)
#pragma unroll
            for (int r = 0; r < 4; r++) acc[i][j][r] = 0.f;

    const int arow = tid >> 1;
    const int half = tid & 1;
    const long rowU4 = (long)(Kp >> 2);
    const long aBase = (long)(bm + arow) * rowU4 + half * 2;
    const int brow = bn + arow;
    const bool bval = brow < N;
    const long bBase = (long)(bval ? brow : 0) * rowU4 + half * 2;
    const uint32_t bbytes = bval ? 16u : 0u;
    const uint32_t aDst0 = sbase + (uint32_t)(arow * RS + half * 2) * 16u;
    const uint32_t bDst0 = aDst0 + (uint32_t)ARR_U4 * 16u;

    const int nSlab = Kp >> 4;

    const uint4* aNxt = Ap + aBase;
    const uint4* bNxt = Wp + bBase;

    auto issueAt = [&](uint32_t so) {
        cpa16(aDst0 + so,       aNxt,     16u);
        cpa16(aDst0 + so + 16u, aNxt + 1, 16u);
        cpa16(bDst0 + so,       bNxt,     bbytes);
        cpa16(bDst0 + so + 16u, bNxt + 1, bbytes);
        aNxt += 4; bNxt += 4;
    };

    uint32_t offA[MT][2], offB[NT];
#pragma unroll
    for (int mt = 0; mt < MT; mt++) {
        int mr = wm * MT * 16 + mt * 16 + grp;
        offA[mt][0] = (uint32_t)((mr * RS + tig) * 16);
        offA[mt][1] = (uint32_t)(((mr + 8) * RS + tig) * 16);
    }
#pragma unroll
    for (int nt = 0; nt < NT; nt++) {
        int nc = wn * NT * 8 + nt * 8 + grp;
        offB[nt] = (uint32_t)((ARR_U4 + nc * RS + tig) * 16);
    }
    const char* sbytes = (const char*)smem4;

    auto computeAt = [&](uint32_t so) {
        const char* sb = sbytes + so;
        uint32_t ah[MT][4], al[MT][4];
        uint32_t bh[NT][2], bl[NT][2];
#pragma unroll
        for (int mt = 0; mt < MT; mt++) {
            uint4 p0 = *(const uint4*)(sb + offA[mt][0]);
            uint4 p1 = *(const uint4*)(sb + offA[mt][1]);
            ah[mt][0] = p0.x; ah[mt][1] = p1.x; ah[mt][2] = p0.z; ah[mt][3] = p1.z;
            al[mt][0] = p0.y; al[mt][1] = p1.y; al[mt][2] = p0.w; al[mt][3] = p1.w;
        }
#pragma unroll
        for (int nt = 0; nt < NT; nt++) {
            uint4 q = *(const uint4*)(sb + offB[nt]);
            bh[nt][0] = q.x; bh[nt][1] = q.z;
            bl[nt][0] = q.y; bl[nt][1] = q.w;
        }
#pragma unroll
        for (int mt = 0; mt < MT; mt++)
#pragma unroll
            for (int nt = 0; nt < NT; nt++) {
                mma_bf16(acc[mt][nt], ah[mt], bl[nt]);   // hi*lo
                mma_bf16(acc[mt][nt], al[mt], bh[nt]);   // lo*hi
                mma_bf16(acc[mt][nt], ah[mt], bh[nt]);   // hi*hi
            }
    };

    // ---- R11 4-stage pipeline ----
#pragma unroll
    for (int s = 0; s < 3; s++) {
        if (s < nSlab) issueAt((uint32_t)(s * STAGE_B));
        CP_COMMIT();
    }
    auto gstep = [&](int slabi, int stage) {
        CP_WAIT(2);
        __syncthreads();
        if (slabi + 3 < nSlab) issueAt((uint32_t)(((slabi + 3) & 3) * STAGE_B));
        CP_COMMIT();
        computeAt((uint32_t)(stage * STAGE_B));
    };
    {
        int slab = 0;
        const int fullN = nSlab & ~3;
        for (; slab < fullN; slab += 4) {
            gstep(slab + 0, 0);
            gstep(slab + 1, 1);
            gstep(slab + 2, 2);
            gstep(slab + 3, 3);
        }
        for (; slab < nSlab; slab++) gstep(slab, slab & 3);
    }

    if constexpr (FUSE == 1) {
        // ---- fused LSTM epilogue (BMT==64, 128 threads) ----
        float* sg = (float*)dynsmem;       // [64][68]
        __syncthreads();
#pragma unroll
        for (int mt = 0; mt < MT; mt++) {
#pragma unroll
            for (int nt = 0; nt < NT; nt++) {
#pragma unroll
                for (int hh = 0; hh < 2; hh++) {
#pragma unroll
                    for (int q = 0; q < 2; q++) {
                        int rl = wm * MT * 16 + mt * 16 + grp + hh * 8;
                        int cl = wn * NT * 8 + nt * 8 + tig * 2 + q;
                        sg[rl * 68 + cl] = acc[mt][nt][hh * 2 + q];
                    }
                }
            }
        }
        __syncthreads();

        const int ebase0 = bn >> 2;
        for (int it = tid; it < 64 * 8; it += 128) {
            int ls = it >> 3, pe = it & 7;
            int s = bm + ls;
            int e0 = ebase0 + pe * 2;
            if (e0 >= 192) continue;
            uint2 p = make_uint2(0, 0);
            if (e0 < E_DIM) {
                int xrow = (s / divA) * mulA + (s % divA) * mulB + tstep;
                const float* xr = xg + (long)xrow * G_DIM;
                float hv[2];
#pragma unroll
                for (int l = 0; l < 2; l++) {
                    int e = e0 + l;
                    float g[4];
#pragma unroll
                    for (int gg = 0; gg < 4; gg++)
                        g[gg] = sg[ls * 68 + pe * 8 + l * 4 + gg]
                              + xr[4 * e + gg] + bih[gg * E_DIM + e] + bhh[gg * E_DIM + e];
                    float cp = cst[(long)s * E_DIM + e];
                    float cn = sigf(g[1]) * cp + sigf(g[0]) * tanhf(g[2]);
                    cst[(long)s * E_DIM + e] = cn;
                    hv[l] = sigf(g[3]) * tanhf(cn);
                }
                p = bfsplit2(hv[0], hv[1]);
            }
            *(uint2*)(hOut + widx((long)s, e0, 192)) = p;
        }
        return;
    }

    // ---- standard epilogue ----
    if (Npck > 0) {
        uint32_t* Cw = (uint32_t*)Cout;
#pragma unroll
        for (int mt = 0; mt < MT; mt++) {
            int r0 = bm + wm * MT * 16 + mt * 16 + grp;
#pragma unroll
            for (int nt = 0; nt < NT; nt++) {
                int cc = bn + wn * NT * 8 + nt * 8 + tig * 2;
                if (cc >= Npck) continue;
#pragma unroll
                for (int hh = 0; hh < 2; hh++) {
                    int rr = r0 + hh * 8;
                    float v0 = 0.f, v1 = 0.f;
                    if (cc < N) {
                        v0 = acc[mt][nt][hh * 2];
                        if (bias) v0 += bias[cc];
                        if (act) v0 = v0 > 0.f ? v0 : (expf(v0) - 1.f);
                    }
                    if (cc + 1 < N) {
                        v1 = acc[mt][nt][hh * 2 + 1];
                        if (bias) v1 += bias[cc + 1];
                        if (act) v1 = v1 > 0.f ? v1 : (expf(v1) - 1.f);
                    }
                    uint2 p = bfsplit2(v0, v1);
                    *(uint2*)(Cw + widx((long)rr, cc, Npck)) = p;
                }
            }
        }
    } else {
        float* Cf = (float*)Cout;
#pragma unroll
        for (int mt = 0; mt < MT; mt++) {
            int r0 = bm + wm * MT * 16 + mt * 16 + grp;
#pragma unroll
            for (int nt = 0; nt < NT; nt++) {
                int cc = bn + wn * NT * 8 + nt * 8 + tig * 2;
#pragma unroll
                for (int hh = 0; hh < 2; hh++) {
                    int rr = r0 + hh * 8;
#pragma unroll
                    for (int q = 0; q < 2; q++) {
                        int gn = cc + q;
                        if (gn >= N) continue;
                        float v = acc[mt][nt][hh * 2 + q];
                        if (bias) v += bias[gn];
                        if (act) v = v > 0.f ? v : (expf(v) - 1.f);
                        Cf[(long)rr * N + gn] = v;
                    }
                }
            }
        }
    }
}

#define SMEM_L (4 * 2 * 128 * 4 * 16)   // 65536
#define SMEM_S (4 * 2 * 64 * 4 * 16)    // 32768

// ---------------------------------------------------------------------------
// Pack kernels. mode 0: plain; 1: gate-interleave rows.
// ---------------------------------------------------------------------------
#define NPACK 14
struct PackTable {
    const float* src[NPACK];
    float* dst[NPACK];
    int rows[NPACK];
    int K[NPACK];
    int Kp[NPACK];
    int mode[NPACK];
};

__global__ void pack_many_kernel(PackTable pt) {
    int which = blockIdx.y;
    int rows = pt.rows[which], K = pt.K[which], Kp = pt.Kp[which];
    int pairs = Kp >> 1;
    long n = (long)rows * pairs;
    long idx = (long)blockIdx.x * blockDim.x + threadIdx.x;
    if (idx >= n) return;
    int r = (int)(idx / pairs);
    int k = (int)(idx % pairs) * 2;
    int sr = (pt.mode[which] == 1) ? ((r & 3) * E_DIM + (r >> 2)) : r;
    const float* s = pt.src[which] + (long)sr * K;
    float v0 = (k < K) ? s[k] : 0.f;
    float v1 = (k + 1 < K) ? s[k + 1] : 0.f;
    uint2 p = bfsplit2(v0, v1);
    *(uint2*)((uint32_t*)pt.dst[which] + widx((long)r, k, Kp)) = p;
}

__global__ void pack_ast_kernel(const float* __restrict__ src, uint32_t* __restrict__ dst) {
    long idx = (long)blockIdx.x * blockDim.x + threadIdx.x;
    if (idx >= (long)M_CE * 512) return;
    int m = (int)(idx / 512);
    int k = (int)(idx % 512) * 2;
    long phys = (long)(m / 48) * 64 + (m % 48);
    const float* s = src + phys * 1024 + k;
    uint2 p = bfsplit2(s[0], s[1]);
    *(uint2*)(dst + widx((long)m, k, 1024)) = p;
}

// ---------------------------------------------------------------------------
// LSTM t=0 step (h0=c0=0); xg gate-interleaved (col = 4*e + gate).
// ---------------------------------------------------------------------------
__global__ void lstm_step0_kernel(
    const float* __restrict__ xg,
    const float* __restrict__ bih, const float* __restrict__ bhh,
    uint32_t* __restrict__ hP, float* __restrict__ c,
    int S, int divA, int mulA, int mulB)
{
    int idx = blockIdx.x * blockDim.x + threadIdx.x;
    if (idx >= S * 96) return;
    int s = idx / 96, pe = idx % 96;
    int e0 = pe * 2;
    uint2 p = make_uint2(0, 0);
    if (e0 < E_DIM) {
        int xrow = (s / divA) * mulA + (s % divA) * mulB;
        const float* xr = xg + (long)xrow * G_DIM;
        float hv[2];
#pragma unroll
        for (int l = 0; l < 2; l++) {
            int e = e0 + l;
            float g[4];
#pragma unroll
            for (int gg = 0; gg < 4; gg++)
                g[gg] = xr[4 * e + gg] + bih[gg * E_DIM + e] + bhh[gg * E_DIM + e];
            float cn = sigf(g[0]) * tanhf(g[2]);
            c[(long)s * E_DIM + e] = cn;
            hv[l] = sigf(g[3]) * tanhf(cn);
        }
        p = bfsplit2(hv[0], hv[1]);
    }
    *(uint2*)(hP + widx((long)s, e0, 192)) = p;
}

// ---------------------------------------------------------------------------
// Concat packed: width 368; [0,180) first, [180,360) second, rest 0.
// ---------------------------------------------------------------------------
__global__ void concat_kernel(
    const uint32_t* __restrict__ first, int firstB,
    const uint32_t* __restrict__ second, int secondB,
    uint32_t* __restrict__ cat, int rows)
{
    int idx = blockIdx.x * blockDim.x + threadIdx.x;
    if (idx >= rows * 184) return;
    int r = idx / 184, pj = idx % 184;
    int j = pj * 2;
    uint2 v = make_uint2(0, 0);
    if (j < E_DIM) {
        long sr = firstB ? 0 : (long)r;
        v = *(const uint2*)(first + widx(sr, j, 192));
    } else if (j < 2 * E_DIM) {
        long sr = secondB ? 0 : (long)r;
        v = *(const uint2*)(second + widx(sr, j - E_DIM, 192));
    }
    *(uint2*)(cat + widx((long)r, j, 368)) = v;
}

// ---------------------------------------------------------------------------
__global__ void pred_kernel(const float* __restrict__ x, const float* __restrict__ w,
                            const float* __restrict__ b, float* __restrict__ out, int rows)
{
    int gwarp = (blockIdx.x * blockDim.x + threadIdx.x) >> 5;
    int lane = threadIdx.x & 31;
    if (gwarp >= rows) return;
    float s = 0.f;
    for (int e = lane; e < E_DIM; e += 32) s += x[(long)gwarp * E_DIM + e] * w[e];
#pragma unroll
    for (int o = 16; o; o >>= 1) s += __shfl_down_sync(0xffffffffu, s, o);
    if (lane == 0) out[gwarp] = s + b[0];
}

// ---------------------------------------------------------------------------
// host side
// ---------------------------------------------------------------------------
static inline void gemm(const float* Ap, const float* Wp, const float* bias, void* C,
                        int M, int N, int Kp, int act, int Npck)
{
    int gL = ((N + 127) / 128) * (M / 128);
    if ((M % 128 == 0) && gL >= 96) {
        dim3 grid((N + 127) / 128, M / 128);
        mma_gemm_pk<128, 2, 4, 2, 0><<<grid, 256, SMEM_L>>>(
            (const uint4*)Ap, (const uint4*)Wp, bias, C, M, N, Kp, act, Npck,
            nullptr, nullptr, nullptr, nullptr, nullptr, 0, 1, 0, 0);
    } else {
        dim3 grid((N + 63) / 64, M / 64);
        mma_gemm_pk<64, 2, 2, 4, 0><<<grid, 128, SMEM_S>>>(
            (const uint4*)Ap, (const uint4*)Wp, bias, C, M, N, Kp, act, Npck,
            nullptr, nullptr, nullptr, nullptr, nullptr, 0, 1, 0, 0);
    }
}

// fused recurrent step: h_out = LSTM(xg[t], h_in @ Whh^T)
static inline void gemm_lstm(const float* hIn, const float* WhhP,
                             const float* xg, const float* bih, const float* bhh,
                             float* c, float* hOut, int S, int t,
                             int divA, int mulA, int mulB)
{
    dim3 grid((G_DIM + 63) / 64, S / 64);   // 12 N-tiles
    mma_gemm_pk<64, 2, 2, 4, 1><<<grid, 128, SMEM_S>>>(
        (const uint4*)hIn, (const uint4*)WhhP, nullptr, nullptr,
        S, G_DIM, 192, 0, 0,
        xg, bih, bhh, c, (uint32_t*)hOut, t, divA, mulA, mulB);
}

extern "C" void kernel_launch(void* const* d_in, const int* in_sizes, int n_in,
                              void* d_out, int out_size)
{
    cudaFuncSetAttribute((const void*)mma_gemm_pk<128, 2, 4, 2, 0>,
                         cudaFuncAttributeMaxDynamicSharedMemorySize, SMEM_L);
    cudaFuncSetAttribute((const void*)mma_gemm_pk<64, 2, 2, 4, 0>,
                         cudaFuncAttributeMaxDynamicSharedMemorySize, SMEM_S);
    cudaFuncSetAttribute((const void*)mma_gemm_pk<64, 2, 2, 4, 1>,
                         cudaFuncAttributeMaxDynamicSharedMemorySize, SMEM_S);

    const float* ast    = (const float*)d_in[0];
    const float* ce_w0  = (const float*)d_in[1];  const float* ce_b0 = (const float*)d_in[2];
    const float* ce_w1  = (const float*)d_in[3];  const float* ce_b1 = (const float*)d_in[4];
    const float* ce_w2  = (const float*)d_in[5];  const float* ce_b2 = (const float*)d_in[6];
    const float* ce_w3  = (const float*)d_in[7];  const float* ce_b3 = (const float*)d_in[8];
    const float* cc_w0  = (const float*)d_in[9];  const float* cc_b0 = (const float*)d_in[10];
    const float* cc_w1  = (const float*)d_in[11]; const float* cc_b1 = (const float*)d_in[12];
    const float* rg_w0  = (const float*)d_in[13]; const float* rg_b0 = (const float*)d_in[14];
    const float* rg_w1  = (const float*)d_in[15]; const float* rg_b1 = (const float*)d_in[16];
    const float* pred_w = (const float*)d_in[17]; const float* pred_b = (const float*)d_in[18];
    const float* cl_Wih = (const float*)d_in[19]; const float* cl_Whh = (const float*)d_in[20];
    const float* cl_bih = (const float*)d_in[21]; const float* cl_bhh = (const float*)d_in[22];
    const float* nl_Wih = (const float*)d_in[23]; const float* nl_Whh = (const float*)d_in[24];
    const float* nl_bih = (const float*)d_in[25]; const float* nl_bhh = (const float*)d_in[26];
    const float* no_comps = (const float*)d_in[27];
    const float* no_nodes = (const float*)d_in[28];
    float* out = (float*)d_out;

    float* S0 = nullptr;
    cudaGetSymbolAddress((void**)&S0, g_scratch4);

    float* astP = S0 + OFF_ASTP;
    float* e0P = S0 + OFF_E0P;   float* e1P = S0 + OFF_E1P;
    float* e2P = S0 + OFF_E2P;   float* edP = S0 + OFF_EDP;
    float* xg  = S0 + OFF_XG;
    float* hA0 = S0 + OFF_HAP;   float* hA1 = S0 + OFF_HAP2;
    float* cA  = S0 + OFF_CA;
    float* catP = S0 + OFF_CATP; float* t2P = S0 + OFF_T2P;
    float* lfP = S0 + OFF_LFP;   float* xgm = S0 + OFF_XGM;
    float* hM0 = S0 + OFF_HMP;   float* hM1 = S0 + OFF_HMP2;
    float* cM  = S0 + OFF_CM;
    float* mdP = S0 + OFF_MDP;   float* xgr = S0 + OFF_XGR;
    float* hR0 = S0 + OFF_HRP;   float* hR1 = S0 + OFF_HRP2;
    float* cR  = S0 + OFF_CR;
    float* pgP = S0 + OFF_PGP;   float* r0P = S0 + OFF_R0P;
    float* r1  = S0 + OFF_R1;
    float* w0P = S0 + OFF_W0P;   float* w1P = S0 + OFF_W1P;
    float* w2P = S0 + OFF_W2P;   float* w3P = S0 + OFF_W3P;
    float* cw0P = S0 + OFF_CW0P; float* cw1P = S0 + OFF_CW1P;
    float* rw0P = S0 + OFF_RW0P; float* rw1P = S0 + OFF_RW1P;
    float* clIP = S0 + OFF_CLIP; float* clHP = S0 + OFF_CLHP;
    float* nlIP = S0 + OFF_NLIP; float* nlHP = S0 + OFF_NLHP;
    float* ncP = S0 + OFF_NCP;   float* nnP = S0 + OFF_NNP;

    // ---- pack weights + constants (LSTM weights gate-interleaved) ----
    PackTable pt;
    const float* srcs[NPACK] = { ce_w0, ce_w1, ce_w2, ce_w3, cc_w0, cc_w1, rg_w0, rg_w1,
                                 cl_Wih, cl_Whh, nl_Wih, nl_Whh, no_comps, no_nodes };
    float* dsts[NPACK] = { w0P, w1P, w2P, w3P, cw0P, cw1P, rw0P, rw1P,
                           clIP, clHP, nlIP, nlHP, ncP, nnP };
    int rws[NPACK] = { 600, 350, 200, 180, 200, 180, 200, 180, 720, 720, 720, 720, 1, 1 };
    int ks[NPACK]  = { 1024, 600, 350, 200, 360, 200, 180, 200, 180, 180, 180, 180, 180, 180 };
    int kps[NPACK] = { 1024, 608, 352, 208, 368, 208, 192, 208, 192, 192, 192, 192, 192, 192 };
    int mds[NPACK] = { 0, 0, 0, 0, 0, 0, 0, 0, 1, 1, 1, 1, 0, 0 };
    for (int i = 0; i < NPACK; i++) {
        pt.src[i] = srcs[i]; pt.dst[i] = dsts[i];
        pt.rows[i] = rws[i]; pt.K[i] = ks[i]; pt.Kp[i] = kps[i]; pt.mode[i] = mds[i];
    }
    {
        long maxn = 600L * 512;
        dim3 g((unsigned)((maxn + 255) / 256), NPACK);
        pack_many_kernel<<<g, 256>>>(pt);
    }
    pack_ast_kernel<<<(int)(((long)M_CE * 512 + 255) / 256), 256>>>(ast, (uint32_t*)astP);

    // ---- Phase A: comp-embedding MLP ----
    gemm(astP, w0P, ce_b0, e0P, M_CE, 600, 1024, 1, 608);
    gemm(e0P,  w1P, ce_b1, e1P, M_CE, 350, 608, 1, 352);
    gemm(e1P,  w2P, ce_b2, e2P, M_CE, 200, 352, 1, 208);
    gemm(e2P,  w3P, ce_b3, edP, M_CE, 180, 208, 1, 192);

    // ---- Phase B: cl LSTM (S=1536, T=8), fused steps ----
    gemm(edP, clIP, nullptr, xg, M_CE, G_DIM, 192, 0, 0);
    {
        int thr = S_CL * 96;
        lstm_step0_kernel<<<(thr + 255) / 256, 256>>>(xg, cl_bih, cl_bhh,
                                                      (uint32_t*)hA0, cA, S_CL, 6, 48, 8);
        float* cur = hA0; float* nxt = hA1;
        for (int t = 1; t < 8; t++) {
            gemm_lstm(cur, clHP, xg, cl_bih, cl_bhh, cA, nxt, S_CL, t, 6, 48, 8);
            float* tmp = cur; cur = nxt; nxt = tmp;
        }
        hA0 = cur;
    }

    // ---- Phase C: leaf concat block ----
    {
        int thr = S_CL * 184;
        concat_kernel<<<(thr + 255) / 256, 256>>>((uint32_t*)nnP, 1, (uint32_t*)hA0, 0,
                                                  (uint32_t*)catP, S_CL);
        gemm(catP, cw0P, cc_b0, t2P, S_CL, 200, 368, 1, 208);
        gemm(t2P,  cw1P, cc_b1, lfP, S_CL, 180, 208, 1, 192);
    }

    // ---- Phase D: mid nl LSTM (S=768, T=2), fused ----
    gemm(lfP, nlIP, nullptr, xgm, S_CL, G_DIM, 192, 0, 0);
    {
        int thr = S_MID * 96;
        lstm_step0_kernel<<<(thr + 255) / 256, 256>>>(xgm, nl_bih, nl_bhh,
                                                      (uint32_t*)hM0, cM, S_MID, 3, 6, 2);
        gemm_lstm(hM0, nlHP, xgm, nl_bih, nl_bhh, cM, hM1, S_MID, 1, 3, 6, 2);
    }

    // ---- Phase E: mid concat block ----
    {
        int thr = S_MID * 184;
        concat_kernel<<<(thr + 255) / 256, 256>>>((uint32_t*)hM1, 0, (uint32_t*)ncP, 1,
                                                  (uint32_t*)catP, S_MID);
        gemm(catP, cw0P, cc_b0, t2P, S_MID, 200, 368, 1, 208);
        gemm(t2P,  cw1P, cc_b1, mdP, S_MID, 180, 208, 1, 192);
    }

    // ---- Phase F: root nl LSTM (S=256, T=3), fused ----
    gemm(mdP, nlIP, nullptr, xgr, S_MID, G_DIM, 192, 0, 0);
    {
        int thr = S_RT * 96;
        lstm_step0_kernel<<<(thr + 255) / 256, 256>>>(xgr, nl_bih, nl_bhh,
                                                      (uint32_t*)hR0, cR, S_RT, 1, 3, 0);
        gemm_lstm(hR0, nlHP, xgr, nl_bih, nl_bhh, cR, hR1, S_RT, 1, 1, 3, 0);
        gemm_lstm(hR1, nlHP, xgr, nl_bih, nl_bhh, cR, hR0, S_RT, 2, 1, 3, 0);
    }

    // ---- Phase G: root concat block ----
    {
        int thr = S_RT * 184;
        concat_kernel<<<(thr + 255) / 256, 256>>>((uint32_t*)hR0, 0, (uint32_t*)ncP, 1,
                                                  (uint32_t*)catP, S_RT);
        gemm(catP, cw0P, cc_b0, t2P, S_RT, 200, 368, 1, 208);
        gemm(t2P,  cw1P, cc_b1, pgP, S_RT, 180, 208, 1, 192);
    }

    // ---- Phase H: regression head ----
    gemm(pgP, rw0P, rg_b0, r0P, S_RT, 200, 192, 1, 208);
    gemm(r0P, rw1P, rg_b1, r1, S_RT, 180, 208, 1, 0);
    pred_kernel<<<(S_RT * 32 + 255) / 256, 256>>>(r1, pred_w, pred_b, out, S_RT);
}